// round 12
// baseline (speedup 1.0000x reference)
#include <cuda_runtime.h>
#include <cuda_bf16.h>
#include <math.h>
#include <stdint.h>

// Problem constants
#define BATCH   16
#define SEQ     512
#define DMODEL  1024
#define NHEAD   16
#define HDIM    64
#define ROWS    (BATCH * SEQ)          // 8192
#define WIN     64                     // WINDOW/2
#define SCALE   0.125f                 // 64^-0.5

// ---------------------------------------------------------------------------
// Scratch (device globals: allocation-free per harness rules)
// ---------------------------------------------------------------------------
__device__ float g_g  [ROWS * DMODEL];
__device__ float g_y  [ROWS * DMODEL];
__device__ __nv_bfloat16 g_qb   [ROWS * DMODEL];
__device__ __nv_bfloat16 g_kb   [ROWS * DMODEL];
__device__ __nv_bfloat16 g_vb   [ROWS * DMODEL];
__device__ __nv_bfloat16 g_attnb[ROWS * DMODEL];
__device__ __nv_bfloat16 g_xb  [ROWS * DMODEL];
__device__ __nv_bfloat16 g_cxb [ROWS * DMODEL];
__device__ __nv_bfloat16 g_wqg [2 * DMODEL * DMODEL];   // [Wq; Wg]
__device__ __nv_bfloat16 g_wkv [2 * DMODEL * DMODEL];   // [Wk; Wv]
__device__ __nv_bfloat16 g_wo  [DMODEL * DMODEL];

// ---------------------------------------------------------------------------
// Helpers
// ---------------------------------------------------------------------------
__device__ __forceinline__ uint32_t smem_u32(const void* p) {
    uint32_t a;
    asm("{ .reg .u64 t; cvta.to.shared.u64 t, %1; cvt.u32.u64 %0, t; }"
        : "=r"(a) : "l"(p));
    return a;
}

__device__ __forceinline__ uint32_t pack_bf16(float lo, float hi) {
    __nv_bfloat162 h = __floats2bfloat162_rn(lo, hi);
    return *(uint32_t*)&h;
}

#define LDSM_X4(r0, r1, r2, r3, addr) \
    asm volatile("ldmatrix.sync.aligned.m8n8.x4.shared.b16 {%0,%1,%2,%3}, [%4];" \
                 : "=r"(r0), "=r"(r1), "=r"(r2), "=r"(r3) : "r"(addr))
#define LDSM_X4_T(r0, r1, r2, r3, addr) \
    asm volatile("ldmatrix.sync.aligned.m8n8.x4.trans.shared.b16 {%0,%1,%2,%3}, [%4];" \
                 : "=r"(r0), "=r"(r1), "=r"(r2), "=r"(r3) : "r"(addr))
#define MMA_BF16(c0, c1, c2, c3, a0, a1, a2, a3, b0, b1) \
    asm volatile("mma.sync.aligned.m16n8k16.row.col.f32.bf16.bf16.f32 " \
                 "{%0,%1,%2,%3}, {%4,%5,%6,%7}, {%8,%9}, {%0,%1,%2,%3};" \
                 : "+f"(c0), "+f"(c1), "+f"(c2), "+f"(c3) \
                 : "r"(a0), "r"(a1), "r"(a2), "r"(a3), "r"(b0), "r"(b1))

// ---------------------------------------------------------------------------
// Fused f32->bf16 conversions
// ---------------------------------------------------------------------------
__global__ __launch_bounds__(256) void conv_acts(
    const float4* __restrict__ X, const float4* __restrict__ Cx,
    uint2* __restrict__ xb, uint2* __restrict__ cxb)
{
    int i = blockIdx.x * 256 + threadIdx.x;
    const float4* src = blockIdx.y ? Cx : X;
    uint2* dst = blockIdx.y ? cxb : xb;
    float4 v = src[i];
    uint2 o;
    o.x = pack_bf16(v.x, v.y);
    o.y = pack_bf16(v.z, v.w);
    dst[i] = o;
}

__global__ __launch_bounds__(256) void conv_weights(
    const float4* __restrict__ Wq, const float4* __restrict__ Wg,
    const float4* __restrict__ Wk, const float4* __restrict__ Wv,
    const float4* __restrict__ Wo,
    uint2* __restrict__ wqg, uint2* __restrict__ wkv, uint2* __restrict__ wo)
{
    int i = blockIdx.x * 256 + threadIdx.x;
    int s = blockIdx.y;
    const float4* src = (s == 0) ? Wq : (s == 1) ? Wg : (s == 2) ? Wk
                       : (s == 3) ? Wv : Wo;
    uint2* dst = (s == 0) ? wqg
               : (s == 1) ? (wqg + DMODEL * DMODEL / 4)
               : (s == 2) ? wkv
               : (s == 3) ? (wkv + DMODEL * DMODEL / 4)
               : wo;
    float4 v = src[i];
    uint2 o;
    o.x = pack_bf16(v.x, v.y);
    o.y = pack_bf16(v.z, v.w);
    dst[i] = o;
}

// ---------------------------------------------------------------------------
// bf16 mma GEMM: CTA 128x128, BK=64, 3 stages (96KB smem), 256 thr, 2 CTA/SM.
// grid.z selects an independent (A, W, outputs) problem -> merged launches.
// Optional fused gated-blend epilogue: y = 0.5*X + 0.5*sigmoid(G)*(acc+bias)
// ---------------------------------------------------------------------------
#define GBM 128
#define GBN 128
#define GBK 64
#define GSTAGES 3
#define GITERS (DMODEL / GBK)                  // 16
#define TILE_BYTES  (GBM * GBK * 2)            // 16384
#define STAGE_BYTES (2 * TILE_BYTES)           // 32768
#define GEMM_SMEM   (GSTAGES * STAGE_BYTES)    // 98304

struct GemmPair {
    const __nv_bfloat16* A;      // [8192,1024]
    const __nv_bfloat16* W;      // [Ntot,1024]
    const float* b0;
    const float* b1;
    void* C0;
    void* C1;
    int obf0, obf1;
};
struct GemmArgs { GemmPair p[2]; };

__device__ __forceinline__ void cp_stage(uint32_t sA, uint32_t sB,
                                         const __nv_bfloat16* __restrict__ Arow,
                                         const __nv_bfloat16* __restrict__ Wrow,
                                         int k0, int t)
{
    #pragma unroll
    for (int i = 0; i < 4; i++) {
        int idx = i * 256 + t;                    // 0..1023
        int row = idx >> 3;                       // 0..127
        int c   = idx & 7;
        uint32_t soff = (uint32_t)(row * 128 + ((c ^ (row & 7)) << 4));
        const __nv_bfloat16* ga = Arow + (size_t)row * DMODEL + k0 + c * 8;
        const __nv_bfloat16* gb = Wrow + (size_t)row * DMODEL + k0 + c * 8;
        asm volatile("cp.async.cg.shared.global [%0], [%1], 16;" :: "r"(sA + soff), "l"(ga));
        asm volatile("cp.async.cg.shared.global [%0], [%1], 16;" :: "r"(sB + soff), "l"(gb));
    }
}

__global__ __launch_bounds__(256, 2)
void gemm_bf16(GemmArgs args, int nsplit,
               const float* __restrict__ epiX,
               const float* __restrict__ epiG)
{
    extern __shared__ char smem[];
    const uint32_t sb = smem_u32(smem);
    const int t = threadIdx.x;
    const int bm = blockIdx.y * GBM;
    const int bn = blockIdx.x * GBN;
    const GemmPair& P = args.p[blockIdx.z];

    const int lane = t & 31;
    const int warp = t >> 5;
    const int grp  = lane >> 2;
    const int tig  = lane & 3;
    const int wm   = warp >> 2;        // 0..1
    const int wn   = warp & 3;         // 0..3
    const int m_base = wm * 64;
    const int n_base = wn * 32;

    const bool hiHalf = (bn >= nsplit);
    void* Cx = hiHalf ? P.C1 : P.C0;
    const float* biasx = hiHalf ? P.b1 : P.b0;
    const int bnl = hiHalf ? (bn - nsplit) : bn;
    const int obf = hiHalf ? P.obf1 : P.obf0;

    const __nv_bfloat16* Arow = P.A + (size_t)bm * DMODEL;
    const __nv_bfloat16* Wrow = P.W + (size_t)bn * DMODEL;

    const int s7 = lane & 7;
    const int hi16 = lane >> 4;
    const int cb   = (lane >> 3) & 1;
    uint32_t rbA[4], rbB[2];
    #pragma unroll
    for (int fi = 0; fi < 4; fi++)
        rbA[fi] = (uint32_t)((m_base + fi * 16 + (lane & 15)) * 128);
    #pragma unroll
    for (int pr = 0; pr < 2; pr++)
        rbB[pr] = (uint32_t)((n_base + pr * 16 + ((lane >> 4) << 3) + (lane & 7)) * 128);

    float acc[4][4][4];
    #pragma unroll
    for (int fi = 0; fi < 4; fi++)
        #pragma unroll
        for (int fj = 0; fj < 4; fj++)
            #pragma unroll
            for (int r = 0; r < 4; r++)
                acc[fi][fj][r] = 0.0f;

    // Prologue: prefetch first GSTAGES-1 stages
    #pragma unroll
    for (int s = 0; s < GSTAGES - 1; s++) {
        cp_stage(sb + s * STAGE_BYTES, sb + s * STAGE_BYTES + TILE_BYTES,
                 Arow, Wrow, s * GBK, t);
        asm volatile("cp.async.commit_group;" ::: "memory");
    }

    for (int it = 0; it < GITERS; it++) {
        asm volatile("cp.async.wait_group 1;" ::: "memory");   // GSTAGES-2
        __syncthreads();

        const int ps = it + GSTAGES - 1;
        if (ps < GITERS) {
            const int s = ps % GSTAGES;
            cp_stage(sb + s * STAGE_BYTES, sb + s * STAGE_BYTES + TILE_BYTES,
                     Arow, Wrow, ps * GBK, t);
        }
        asm volatile("cp.async.commit_group;" ::: "memory");

        const uint32_t sA = sb + (it % GSTAGES) * STAGE_BYTES;
        const uint32_t sB = sA + TILE_BYTES;

        #pragma unroll
        for (int ks = 0; ks < 4; ks++) {
            const uint32_t coA = (uint32_t)(((2 * ks + hi16) ^ s7) << 4);
            const uint32_t coB = (uint32_t)(((2 * ks + cb)   ^ s7) << 4);

            uint32_t a[4][4];
            #pragma unroll
            for (int fi = 0; fi < 4; fi++)
                LDSM_X4(a[fi][0], a[fi][1], a[fi][2], a[fi][3], sA + rbA[fi] + coA);

            uint32_t b[2][4];
            #pragma unroll
            for (int pr = 0; pr < 2; pr++)
                LDSM_X4(b[pr][0], b[pr][1], b[pr][2], b[pr][3], sB + rbB[pr] + coB);

            #pragma unroll
            for (int fi = 0; fi < 4; fi++)
                #pragma unroll
                for (int fj = 0; fj < 4; fj++) {
                    const int pr = fj >> 1, hf = (fj & 1) << 1;
                    MMA_BF16(acc[fi][fj][0], acc[fi][fj][1], acc[fi][fj][2], acc[fi][fj][3],
                             a[fi][0], a[fi][1], a[fi][2], a[fi][3],
                             b[pr][hf], b[pr][hf + 1]);
                }
        }
    }

    // Epilogue
    #pragma unroll
    for (int fi = 0; fi < 4; fi++) {
        const int m0 = bm + m_base + fi * 16 + grp;
        #pragma unroll
        for (int fj = 0; fj < 4; fj++) {
            const int n = bnl + n_base + fj * 8 + tig * 2;
            const float2 bv = *(const float2*)&biasx[n];
            float v00 = acc[fi][fj][0] + bv.x;
            float v01 = acc[fi][fj][1] + bv.y;
            float v10 = acc[fi][fj][2] + bv.x;
            float v11 = acc[fi][fj][3] + bv.y;
            const size_t i0 = (size_t)m0 * DMODEL + n;
            const size_t i1 = (size_t)(m0 + 8) * DMODEL + n;
            if (epiX) {
                float2 x0 = *(const float2*)&epiX[i0];
                float2 x1 = *(const float2*)&epiX[i1];
                float2 g0 = *(const float2*)&epiG[i0];
                float2 g1 = *(const float2*)&epiG[i1];
                v00 = 0.5f * x0.x + 0.5f * v00 / (1.0f + __expf(-g0.x));
                v01 = 0.5f * x0.y + 0.5f * v01 / (1.0f + __expf(-g0.y));
                v10 = 0.5f * x1.x + 0.5f * v10 / (1.0f + __expf(-g1.x));
                v11 = 0.5f * x1.y + 0.5f * v11 / (1.0f + __expf(-g1.y));
            }
            if (obf) {
                __nv_bfloat16* cp = (__nv_bfloat16*)Cx;
                *(uint32_t*)&cp[i0] = pack_bf16(v00, v01);
                *(uint32_t*)&cp[i1] = pack_bf16(v10, v11);
            } else {
                float* cp = (float*)Cx;
                *(float2*)&cp[i0] = make_float2(v00, v01);
                *(float2*)&cp[i1] = make_float2(v10, v11);
            }
        }
    }
}

// ---------------------------------------------------------------------------
// Windowed attention on tensor cores (R6-proven).
// ---------------------------------------------------------------------------
#define KRANGE 192
#define NJT    24
#define ATTN_SMEM ((64 + KRANGE + KRANGE) * 128)   // 57344 B

__global__ __launch_bounds__(128)
void attn_mma(const __nv_bfloat16* __restrict__ Q,
              const __nv_bfloat16* __restrict__ K,
              const __nv_bfloat16* __restrict__ V,
              __nv_bfloat16* __restrict__ O)
{
    extern __shared__ char smem[];
    const uint32_t sQ = smem_u32(smem);
    const uint32_t sK = sQ + 64 * 128;
    const uint32_t sV = sK + KRANGE * 128;

    const int qt   = blockIdx.x;
    const int h    = blockIdx.y;
    const int b    = blockIdx.z;
    const int t    = threadIdx.x;
    const int lane = t & 31;
    const int w    = t >> 5;
    const int grp  = lane >> 2;
    const int tig  = lane & 3;

    const int q0    = qt * 64;
    const int kbase = q0 - WIN;

    const __nv_bfloat16* Qg = Q + ((size_t)b * SEQ) * DMODEL + h * HDIM;
    const __nv_bfloat16* Kg = K + ((size_t)b * SEQ) * DMODEL + h * HDIM;
    const __nv_bfloat16* Vg = V + ((size_t)b * SEQ) * DMODEL + h * HDIM;

    for (int i = t; i < 64 * 8; i += 128) {
        int row = i >> 3, c = i & 7;
        uint32_t dst = sQ + row * 128 + ((c ^ (row & 7)) << 4);
        const __nv_bfloat16* src = Qg + (size_t)(q0 + row) * DMODEL + c * 8;
        asm volatile("cp.async.cg.shared.global [%0], [%1], 16;" :: "r"(dst), "l"(src));
    }
    for (int i = t; i < KRANGE * 8; i += 128) {
        int row = i >> 3, c = i & 7;
        int jg = kbase + row;
        uint32_t off = row * 128 + ((c ^ (row & 7)) << 4);
        if ((unsigned)jg < (unsigned)SEQ) {
            const __nv_bfloat16* srck = Kg + (size_t)jg * DMODEL + c * 8;
            const __nv_bfloat16* srcv = Vg + (size_t)jg * DMODEL + c * 8;
            asm volatile("cp.async.cg.shared.global [%0], [%1], 16;" :: "r"(sK + off), "l"(srck));
            asm volatile("cp.async.cg.shared.global [%0], [%1], 16;" :: "r"(sV + off), "l"(srcv));
        } else {
            asm volatile("st.shared.v4.b32 [%0], {%1,%1,%1,%1};" :: "r"(sK + off), "r"(0u));
            asm volatile("st.shared.v4.b32 [%0], {%1,%1,%1,%1};" :: "r"(sV + off), "r"(0u));
        }
    }
    asm volatile("cp.async.commit_group;" ::: "memory");
    asm volatile("cp.async.wait_group 0;" ::: "memory");
    __syncthreads();

    const int s7 = lane & 7;
    const int m_base = w * 16;
    const uint32_t rowA = (uint32_t)((m_base + (lane & 15)) * 128);
    const int hi16 = lane >> 4;
    const uint32_t rowBoff = (uint32_t)((((lane >> 4) << 3) + (lane & 7)) * 128);
    const int cb = (lane >> 3) & 1;

    float sc[NJT][4];
    #pragma unroll
    for (int nt = 0; nt < NJT; nt++)
        #pragma unroll
        for (int r = 0; r < 4; r++)
            sc[nt][r] = 0.0f;

    #pragma unroll
    for (int ks = 0; ks < 4; ks++) {
        const uint32_t coA = (uint32_t)(((2 * ks + hi16) ^ s7) << 4);
        const uint32_t coB = (uint32_t)(((2 * ks + cb) ^ s7) << 4);
        uint32_t a0, a1, a2, a3;
        LDSM_X4(a0, a1, a2, a3, sQ + rowA + coA);
        #pragma unroll
        for (int jt = 0; jt < 12; jt++) {
            uint32_t b0, b1, b2, b3;
            LDSM_X4(b0, b1, b2, b3, sK + (uint32_t)(jt * 16 * 128) + rowBoff + coB);
            MMA_BF16(sc[2 * jt][0], sc[2 * jt][1], sc[2 * jt][2], sc[2 * jt][3],
                     a0, a1, a2, a3, b0, b1);
            MMA_BF16(sc[2 * jt + 1][0], sc[2 * jt + 1][1], sc[2 * jt + 1][2], sc[2 * jt + 1][3],
                     a0, a1, a2, a3, b2, b3);
        }
    }

    const int qi0 = q0 + m_base + grp;
    const int qi1 = qi0 + 8;
    #pragma unroll
    for (int nt = 0; nt < NJT; nt++) {
        const int jg0 = kbase + nt * 8 + tig * 2;
        const int jg1 = jg0 + 1;
        bool v00 = ((unsigned)jg0 < (unsigned)SEQ) && ((unsigned)(qi0 - jg0 + WIN) <= 2u * WIN);
        bool v01 = ((unsigned)jg1 < (unsigned)SEQ) && ((unsigned)(qi0 - jg1 + WIN) <= 2u * WIN);
        bool v10 = ((unsigned)jg0 < (unsigned)SEQ) && ((unsigned)(qi1 - jg0 + WIN) <= 2u * WIN);
        bool v11 = ((unsigned)jg1 < (unsigned)SEQ) && ((unsigned)(qi1 - jg1 + WIN) <= 2u * WIN);
        sc[nt][0] = v00 ? sc[nt][0] * SCALE : -1e30f;
        sc[nt][1] = v01 ? sc[nt][1] * SCALE : -1e30f;
        sc[nt][2] = v10 ? sc[nt][2] * SCALE : -1e30f;
        sc[nt][3] = v11 ? sc[nt][3] * SCALE : -1e30f;
    }

    float m0 = -1e30f, m1 = -1e30f;
    #pragma unroll
    for (int nt = 0; nt < NJT; nt++) {
        m0 = fmaxf(m0, fmaxf(sc[nt][0], sc[nt][1]));
        m1 = fmaxf(m1, fmaxf(sc[nt][2], sc[nt][3]));
    }
    #pragma unroll
    for (int o = 1; o <= 2; o <<= 1) {
        m0 = fmaxf(m0, __shfl_xor_sync(0xffffffffu, m0, o));
        m1 = fmaxf(m1, __shfl_xor_sync(0xffffffffu, m1, o));
    }
    float s0 = 0.0f, s1 = 0.0f;
    #pragma unroll
    for (int nt = 0; nt < NJT; nt++) {
        sc[nt][0] = __expf(sc[nt][0] - m0);
        sc[nt][1] = __expf(sc[nt][1] - m0);
        sc[nt][2] = __expf(sc[nt][2] - m1);
        sc[nt][3] = __expf(sc[nt][3] - m1);
        s0 += sc[nt][0] + sc[nt][1];
        s1 += sc[nt][2] + sc[nt][3];
    }
    #pragma unroll
    for (int o = 1; o <= 2; o <<= 1) {
        s0 += __shfl_xor_sync(0xffffffffu, s0, o);
        s1 += __shfl_xor_sync(0xffffffffu, s1, o);
    }
    const float inv0 = 1.0f / s0;
    const float inv1 = 1.0f / s1;

    float ov[8][4];
    #pragma unroll
    for (int nt = 0; nt < 8; nt++)
        #pragma unroll
        for (int r = 0; r < 4; r++)
            ov[nt][r] = 0.0f;

    const uint32_t rowV = (uint32_t)((lane & 15) * 128);
    #pragma unroll
    for (int kj = 0; kj < 12; kj++) {
        uint32_t ra0 = pack_bf16(sc[2 * kj][0] * inv0,     sc[2 * kj][1] * inv0);
        uint32_t ra1 = pack_bf16(sc[2 * kj][2] * inv1,     sc[2 * kj][3] * inv1);
        uint32_t ra2 = pack_bf16(sc[2 * kj + 1][0] * inv0, sc[2 * kj + 1][1] * inv0);
        uint32_t ra3 = pack_bf16(sc[2 * kj + 1][2] * inv1, sc[2 * kj + 1][3] * inv1);
        const uint32_t vbase = sV + (uint32_t)(kj * 16 * 128) + rowV;
        #pragma unroll
        for (int dt = 0; dt < 4; dt++) {
            const int row = kj * 16 + (lane & 15);
            const uint32_t cd = (uint32_t)(dt * 2 + (lane >> 4));
            uint32_t b0, b1, b2, b3;
            LDSM_X4_T(b0, b1, b2, b3, vbase + ((cd ^ (uint32_t)(row & 7)) << 4));
            MMA_BF16(ov[2 * dt][0], ov[2 * dt][1], ov[2 * dt][2], ov[2 * dt][3],
                     ra0, ra1, ra2, ra3, b0, b1);
            MMA_BF16(ov[2 * dt + 1][0], ov[2 * dt + 1][1], ov[2 * dt + 1][2], ov[2 * dt + 1][3],
                     ra0, ra1, ra2, ra3, b2, b3);
        }
    }

    __nv_bfloat16* O0 = O + ((size_t)b * SEQ + qi0) * DMODEL + h * HDIM;
    __nv_bfloat16* O1 = O + ((size_t)b * SEQ + qi1) * DMODEL + h * HDIM;
    #pragma unroll
    for (int nt = 0; nt < 8; nt++) {
        const int d = nt * 8 + tig * 2;
        *(uint32_t*)&O0[d] = pack_bf16(ov[nt][0], ov[nt][1]);
        *(uint32_t*)&O1[d] = pack_bf16(ov[nt][2], ov[nt][3]);
    }
}

// ---------------------------------------------------------------------------
// LayerNorm over y
// ---------------------------------------------------------------------------
__global__ __launch_bounds__(256) void fused_ln(
    const float* __restrict__ Y,
    const float* __restrict__ gamma,
    const float* __restrict__ beta,
    float* __restrict__ out)
{
    const int r = blockIdx.x;
    const int t = threadIdx.x;
    const float* y = Y + (size_t)r * DMODEL;

    float v[4];
    float lsum = 0.0f, lsq = 0.0f;
    #pragma unroll
    for (int i = 0; i < 4; i++) {
        int c = t + i * 256;
        v[i] = y[c];
        lsum += v[i];
        lsq  += v[i] * v[i];
    }

    #pragma unroll
    for (int o = 16; o > 0; o >>= 1) {
        lsum += __shfl_xor_sync(0xffffffffu, lsum, o);
        lsq  += __shfl_xor_sync(0xffffffffu, lsq, o);
    }
    __shared__ float red[2][8];
    const int w = t >> 5, lane = t & 31;
    if (lane == 0) { red[0][w] = lsum; red[1][w] = lsq; }
    __syncthreads();
    float tsum = 0.0f, tsq = 0.0f;
    #pragma unroll
    for (int i = 0; i < 8; i++) { tsum += red[0][i]; tsq += red[1][i]; }

    const float mean = tsum * (1.0f / DMODEL);
    const float var  = tsq * (1.0f / DMODEL) - mean * mean;
    const float rstd = rsqrtf(var + 1e-5f);

    float* o = out + (size_t)r * DMODEL;
    #pragma unroll
    for (int i = 0; i < 4; i++) {
        int c = t + i * 256;
        o[c] = (v[i] - mean) * rstd * gamma[c] + beta[c];
    }
}

// ---------------------------------------------------------------------------
// Launch
// ---------------------------------------------------------------------------
extern "C" void kernel_launch(void* const* d_in, const int* in_sizes, int n_in,
                              void* d_out, int out_size)
{
    const float* X     = (const float*)d_in[0];
    const float* Cx    = (const float*)d_in[1];
    const float* Wq    = (const float*)d_in[2];
    const float* bq    = (const float*)d_in[3];
    const float* Wk    = (const float*)d_in[4];
    const float* bk    = (const float*)d_in[5];
    const float* Wv    = (const float*)d_in[6];
    const float* bv    = (const float*)d_in[7];
    const float* Wo    = (const float*)d_in[8];
    const float* bo    = (const float*)d_in[9];
    const float* Wg    = (const float*)d_in[10];
    const float* bg    = (const float*)d_in[11];
    const float* gamma = (const float*)d_in[12];
    const float* beta  = (const float*)d_in[13];
    float* out = (float*)d_out;

    float *g, *y;
    __nv_bfloat16 *qb, *kb, *vb, *attnb, *xb, *cxb, *wqg, *wkv, *wo;
    cudaGetSymbolAddress((void**)&g,     g_g);
    cudaGetSymbolAddress((void**)&y,     g_y);
    cudaGetSymbolAddress((void**)&qb,    g_qb);
    cudaGetSymbolAddress((void**)&kb,    g_kb);
    cudaGetSymbolAddress((void**)&vb,    g_vb);
    cudaGetSymbolAddress((void**)&attnb, g_attnb);
    cudaGetSymbolAddress((void**)&xb,    g_xb);
    cudaGetSymbolAddress((void**)&cxb,   g_cxb);
    cudaGetSymbolAddress((void**)&wqg,   g_wqg);
    cudaGetSymbolAddress((void**)&wkv,   g_wkv);
    cudaGetSymbolAddress((void**)&wo,    g_wo);

    cudaFuncSetAttribute(gemm_bf16, cudaFuncAttributeMaxDynamicSharedMemorySize, GEMM_SMEM);
    cudaFuncSetAttribute(attn_mma, cudaFuncAttributeMaxDynamicSharedMemorySize, ATTN_SMEM);

    // Fused conversions
    dim3 act_grid(ROWS * DMODEL / 4 / 256, 2);
    conv_acts<<<act_grid, 256>>>((const float4*)X, (const float4*)Cx,
                                 (uint2*)xb, (uint2*)cxb);
    dim3 w_grid(DMODEL * DMODEL / 4 / 256, 5);
    conv_weights<<<w_grid, 256>>>((const float4*)Wq, (const float4*)Wg,
                                  (const float4*)Wk, (const float4*)Wv,
                                  (const float4*)Wo,
                                  (uint2*)wqg, (uint2*)wkv, (uint2*)wo);

    // Merged fused projections: z=0 -> [Q|G] from X; z=1 -> [K|V] from Cx
    GemmArgs pa;
    pa.p[0] = { xb,  wqg, bq, bg, (void*)qb, (void*)g,  1, 0 };
    pa.p[1] = { cxb, wkv, bk, bv, (void*)kb, (void*)vb, 1, 1 };
    dim3 proj_grid(2 * DMODEL / GBN, ROWS / GBM, 2);   // (16, 64, 2)
    gemm_bf16<<<proj_grid, 256, GEMM_SMEM>>>(pa, DMODEL, nullptr, nullptr);

    // Tensor-core windowed attention
    dim3 attn_grid(SEQ / 64, NHEAD, BATCH);
    attn_mma<<<attn_grid, 128, ATTN_SMEM>>>(qb, kb, vb, attnb);

    // Output projection with fused gate+blend epilogue -> y
    GemmArgs po;
    po.p[0] = { attnb, wo, bo, bo, (void*)y, (void*)y, 0, 0 };
    po.p[1] = po.p[0];
    dim3 o_grid(DMODEL / GBN, ROWS / GBM, 1);          // (8, 64)
    gemm_bf16<<<o_grid, 256, GEMM_SMEM>>>(po, DMODEL, X, g);

    // LayerNorm
    fused_ln<<<ROWS, 256>>>(y, gamma, beta, out);
}